// round 14
// baseline (speedup 1.0000x reference)
#include <cuda_runtime.h>
#include <cuda_bf16.h>
#include <cuda_fp16.h>
#include <cstdint>

// Problem constants (match reference_code)
#define NN 50000
#define EE 800000
#define FIN 256
#define FOUT 64

#define NBLK 49   // ceil(NN / 1024)

// Scratch (no cudaMalloc allowed) — static __device__ globals.
__device__ int    g_cnt[NN];          // in-degree (w/o self loop)
__device__ int    g_fill[NN];         // bucket fill cursor (pre-init to offsets)
__device__ int    g_off[NN + 1];      // CSR offsets
__device__ int    g_bsum[64];         // per-block sums for scan
__device__ int    g_nbr[EE];          // CSR: src node per incoming edge (4B/edge)
__device__ float  g_deg[NN];          // dinv = rsqrt(deg)
__device__ __half g_h16[NN * FOUT];   // h = x @ W, fp16 (128B per row)

// ---------------------------------------------------------------------------
__device__ __forceinline__ uint32_t pk2(float lo, float hi) {
    uint32_t d;
    asm("cvt.rn.bf16x2.f32 %0, %1, %2;" : "=r"(d) : "f"(hi), "f"(lo));
    return d;
}
__device__ __forceinline__ float f_lo16(uint32_t u) { return __uint_as_float(u << 16); }
__device__ __forceinline__ float f_hi16(uint32_t u) { return __uint_as_float(u & 0xffff0000u); }

__device__ __forceinline__ void mma_bf16(float* c, const uint32_t* a, uint32_t b0, uint32_t b1) {
    asm volatile(
        "mma.sync.aligned.m16n8k16.row.col.f32.bf16.bf16.f32 "
        "{%0,%1,%2,%3}, {%4,%5,%6,%7}, {%8,%9}, {%0,%1,%2,%3};"
        : "+f"(c[0]), "+f"(c[1]), "+f"(c[2]), "+f"(c[3])
        : "r"(a[0]), "r"(a[1]), "r"(a[2]), "r"(a[3]), "r"(b0), "r"(b1));
}

// ---------------------------------------------------------------------------
// K1: zero counters
__global__ void k_zero() {
    int i = blockIdx.x * blockDim.x + threadIdx.x;
    if (i < NN) g_cnt[i] = 0;
}

// K2: in-degree count over edge dst (4 edges/thread, int4 loads)
__global__ void k_count(const int* __restrict__ dst) {
    int e0 = (blockIdx.x * blockDim.x + threadIdx.x) * 4;
    if (e0 >= EE) return;
    int4 d4 = *reinterpret_cast<const int4*>(dst + e0);
    atomicAdd(&g_cnt[d4.x], 1);
    atomicAdd(&g_cnt[d4.y], 1);
    atomicAdd(&g_cnt[d4.z], 1);
    atomicAdd(&g_cnt[d4.w], 1);
}

// K3a: per-block (1024 elems) sums, coalesced
__global__ __launch_bounds__(1024) void k_scan_a() {
    __shared__ int ws[32];
    const int t = threadIdx.x;
    int idx = blockIdx.x * 1024 + t;
    int v = (idx < NN) ? g_cnt[idx] : 0;
    for (int o = 16; o > 0; o >>= 1) v += __shfl_down_sync(0xffffffffu, v, o);
    if ((t & 31) == 0) ws[t >> 5] = v;
    __syncthreads();
    if (t < 32) {
        int s = ws[t];
        for (int o = 16; o > 0; o >>= 1) s += __shfl_down_sync(0xffffffffu, s, o);
        if (t == 0) g_bsum[blockIdx.x] = s;
    }
}

// K3b: per-block exclusive scan -> g_off, g_fill (cursor), g_deg.
__global__ __launch_bounds__(1024) void k_scan_c() {
    __shared__ int ws[32];
    __shared__ int bpre_s;
    const int t = threadIdx.x;
    const int lane = t & 31;
    const int wid = t >> 5;
    int idx = blockIdx.x * 1024 + t;
    int c = (idx < NN) ? g_cnt[idx] : 0;

    int incl = c;
    for (int o = 1; o < 32; o <<= 1) {
        int u = __shfl_up_sync(0xffffffffu, incl, o);
        if (lane >= o) incl += u;
    }
    if (lane == 31) ws[wid] = incl;

    if (wid == 1) {
        int accp = 0;
        for (int j = lane; j < blockIdx.x; j += 32) accp += g_bsum[j];
        for (int o = 16; o > 0; o >>= 1) accp += __shfl_down_sync(0xffffffffu, accp, o);
        if (lane == 0) bpre_s = accp;
    }
    __syncthreads();
    if (wid == 0) {
        int wv = ws[lane];
        for (int o = 1; o < 32; o <<= 1) {
            int u = __shfl_up_sync(0xffffffffu, wv, o);
            if (lane >= o) wv += u;
        }
        ws[lane] = wv;
    }
    __syncthreads();
    int excl = incl - c + (wid ? ws[wid - 1] : 0);

    if (idx < NN) {
        int off = bpre_s + excl;
        g_off[idx]  = off;
        g_fill[idx] = off;
        g_deg[idx]  = rsqrtf((float)(c + 1));
    }
    if (blockIdx.x == 0 && t == 0) g_off[NN] = EE;
}

// K4: bucket fill — cursor holds offsets; 4 edges/thread; 4B/edge store.
__global__ void k_fill(const int* __restrict__ src, const int* __restrict__ dst) {
    int e0 = (blockIdx.x * blockDim.x + threadIdx.x) * 4;
    if (e0 >= EE) return;
    int4 s4 = *reinterpret_cast<const int4*>(src + e0);
    int4 d4 = *reinterpret_cast<const int4*>(dst + e0);
    int p0 = atomicAdd(&g_fill[d4.x], 1);
    int p1 = atomicAdd(&g_fill[d4.y], 1);
    int p2 = atomicAdd(&g_fill[d4.z], 1);
    int p3 = atomicAdd(&g_fill[d4.w], 1);
    g_nbr[p0] = s4.x;
    g_nbr[p1] = s4.y;
    g_nbr[p2] = s4.z;
    g_nbr[p3] = s4.w;
}

// ---------------------------------------------------------------------------
// K5: mma.sync bf16 GEMM, split-bf16, permuted-K fragments, SOFTWARE-PIPELINED:
// per k-step: convert current float4s -> frags (frees regs), issue NEXT step's
// A-loads, then 12 MMAs — loads fly during the MMA block.

#define PAD_K 272
#define B_HI_OFF 0
#define B_LO_OFF (64 * PAD_K)               // in ushort units
#define GEMM_SMEM (2 * 64 * PAD_K * 2)      // bytes = 69632

__global__ __launch_bounds__(512, 2) void k_gemm_mma(
    const float* __restrict__ x, const float* __restrict__ W)
{
    extern __shared__ __align__(16) ushort Bs[];   // [2][64][PAD_K] bf16 bits

    const int t    = threadIdx.x;
    const int wid  = t >> 5;
    const int lane = t & 31;
    const int g    = lane >> 2;
    const int tig  = lane & 3;

    // ---- stage W -> smem bf16 hi/lo, [n][k] layout ----
#pragma unroll 8
    for (int it = 0; it < 32; ++it) {
        int idx = t + it * 512;
        int k = idx >> 6;
        int n = idx & 63;
        float w = W[k * FOUT + n];
        uint32_t hp = pk2(w, 0.f);
        Bs[B_HI_OFF + n * PAD_K + k] = (ushort)(hp & 0xffffu);
        Bs[B_LO_OFF + n * PAD_K + k] =
            (ushort)(pk2(w - f_lo16(hp), 0.f) & 0xffffu);
    }
    __syncthreads();

    const int stripe = wid & 7;
    const int nhalf  = wid >> 3;
    const int row0   = blockIdx.x * 128 + stripe * 16;

    const int row1 = row0 + g;
    const int row2 = row1 + 8;
    const bool v1 = (row1 < NN);
    const bool v2 = (row2 < NN);
    const float* xr1 = x + (size_t)row1 * FIN;
    const float* xr2 = x + (size_t)row2 * FIN;

    float acc[4][4];
#pragma unroll
    for (int i = 0; i < 4; ++i)
#pragma unroll
        for (int j = 0; j < 4; ++j) acc[i][j] = 0.0f;

    // prologue: load step 0
    int kb4 = tig * 4;
    float4 q1 = v1 ? *reinterpret_cast<const float4*>(xr1 + kb4)
                   : make_float4(0.f, 0.f, 0.f, 0.f);
    float4 q2 = v2 ? *reinterpret_cast<const float4*>(xr2 + kb4)
                   : make_float4(0.f, 0.f, 0.f, 0.f);

#pragma unroll
    for (int s = 0; s < 16; ++s) {
        // convert current (q1,q2 die here)
        uint32_t a_hi[4], a_lo[4];
        a_hi[0] = pk2(q1.x, q1.y); a_lo[0] = pk2(q1.x - f_lo16(a_hi[0]), q1.y - f_hi16(a_hi[0]));
        a_hi[1] = pk2(q2.x, q2.y); a_lo[1] = pk2(q2.x - f_lo16(a_hi[1]), q2.y - f_hi16(a_hi[1]));
        a_hi[2] = pk2(q1.z, q1.w); a_lo[2] = pk2(q1.z - f_lo16(a_hi[2]), q1.w - f_hi16(a_hi[2]));
        a_hi[3] = pk2(q2.z, q2.w); a_lo[3] = pk2(q2.z - f_lo16(a_hi[3]), q2.w - f_hi16(a_hi[3]));

        // issue next step's loads — in flight during the MMA block below
        const int kcur = kb4;
        if (s < 15) {
            kb4 += 16;
            q1 = v1 ? *reinterpret_cast<const float4*>(xr1 + kb4)
                    : make_float4(0.f, 0.f, 0.f, 0.f);
            q2 = v2 ? *reinterpret_cast<const float4*>(xr2 + kb4)
                    : make_float4(0.f, 0.f, 0.f, 0.f);
        }

#pragma unroll
        for (int nt = 0; nt < 4; ++nt) {
            int n = nhalf * 32 + nt * 8 + g;
            uint2 bh = *reinterpret_cast<const uint2*>(&Bs[B_HI_OFF + n * PAD_K + kcur]);
            uint2 bl = *reinterpret_cast<const uint2*>(&Bs[B_LO_OFF + n * PAD_K + kcur]);
            mma_bf16(acc[nt], a_hi, bh.x, bh.y);
            mma_bf16(acc[nt], a_hi, bl.x, bl.y);
            mma_bf16(acc[nt], a_lo, bh.x, bh.y);
        }
    }

    // ---- epilogue: write h as fp16 ----
#pragma unroll
    for (int nt = 0; nt < 4; ++nt) {
        int c0 = nhalf * 32 + nt * 8 + tig * 2;
        if (v1) {
            __half2 hv = __floats2half2_rn(acc[nt][0], acc[nt][1]);
            *reinterpret_cast<__half2*>(&g_h16[(size_t)row1 * FOUT + c0]) = hv;
        }
        if (v2) {
            __half2 hv = __floats2half2_rn(acc[nt][2], acc[nt][3]);
            *reinterpret_cast<__half2*>(&g_h16[(size_t)row2 * FOUT + c0]) = hv;
        }
    }
}

// ---------------------------------------------------------------------------
// K6: CSR gather on fp16 h. 2 nodes/warp, fp32 accumulation, x8 unroll
// (8 independent h-row loads in flight per half-warp).
__global__ __launch_bounds__(256) void k_gather(
    const float* __restrict__ bias, float* __restrict__ out)
{
    const int warp = blockIdx.x * 8 + (threadIdx.x >> 5);
    const int lane = threadIdx.x & 31;
    const int half = lane >> 4;
    const int hl   = lane & 15;
    const int node = warp * 2 + half;
    if (node >= NN) return;

    const float dinv = g_deg[node];
    const int beg = g_off[node];
    const int end = g_off[node + 1];

    uint2 su = *reinterpret_cast<const uint2*>(&g_h16[(size_t)node * FOUT + hl * 4]);
    float2 s01 = __half22float2(*reinterpret_cast<__half2*>(&su.x));
    float2 s23 = __half22float2(*reinterpret_cast<__half2*>(&su.y));
    const float sl = dinv * dinv;
    float4 a = make_float4(s01.x * sl, s01.y * sl, s23.x * sl, s23.y * sl);

    int j = beg;
    for (; j + 8 <= end; j += 8) {
        int sI[8];
#pragma unroll
        for (int u = 0; u < 8; ++u) sI[u] = g_nbr[j + u];
        uint2 hU[8];
#pragma unroll
        for (int u = 0; u < 8; ++u)
            hU[u] = *reinterpret_cast<const uint2*>(&g_h16[(size_t)sI[u] * FOUT + hl * 4]);
#pragma unroll
        for (int u = 0; u < 8; ++u) {
            float nw = dinv * g_deg[sI[u]];
            float2 fa = __half22float2(*reinterpret_cast<__half2*>(&hU[u].x));
            float2 fb = __half22float2(*reinterpret_cast<__half2*>(&hU[u].y));
            a.x = fmaf(fa.x, nw, a.x); a.y = fmaf(fa.y, nw, a.y);
            a.z = fmaf(fb.x, nw, a.z); a.w = fmaf(fb.y, nw, a.w);
        }
    }
    for (; j + 2 <= end; j += 2) {
        int s0 = g_nbr[j], s1 = g_nbr[j + 1];
        float n0 = dinv * g_deg[s0];
        float n1 = dinv * g_deg[s1];
        uint2 u0 = *reinterpret_cast<const uint2*>(&g_h16[(size_t)s0 * FOUT + hl * 4]);
        uint2 u1 = *reinterpret_cast<const uint2*>(&g_h16[(size_t)s1 * FOUT + hl * 4]);
        float2 f0a = __half22float2(*reinterpret_cast<__half2*>(&u0.x));
        float2 f0b = __half22float2(*reinterpret_cast<__half2*>(&u0.y));
        float2 f1a = __half22float2(*reinterpret_cast<__half2*>(&u1.x));
        float2 f1b = __half22float2(*reinterpret_cast<__half2*>(&u1.y));
        a.x = fmaf(f0a.x, n0, a.x); a.y = fmaf(f0a.y, n0, a.y);
        a.z = fmaf(f0b.x, n0, a.z); a.w = fmaf(f0b.y, n0, a.w);
        a.x = fmaf(f1a.x, n1, a.x); a.y = fmaf(f1a.y, n1, a.y);
        a.z = fmaf(f1b.x, n1, a.z); a.w = fmaf(f1b.y, n1, a.w);
    }
    if (j < end) {
        int s0 = g_nbr[j];
        float n0 = dinv * g_deg[s0];
        uint2 u0 = *reinterpret_cast<const uint2*>(&g_h16[(size_t)s0 * FOUT + hl * 4]);
        float2 f0a = __half22float2(*reinterpret_cast<__half2*>(&u0.x));
        float2 f0b = __half22float2(*reinterpret_cast<__half2*>(&u0.y));
        a.x = fmaf(f0a.x, n0, a.x); a.y = fmaf(f0a.y, n0, a.y);
        a.z = fmaf(f0b.x, n0, a.z); a.w = fmaf(f0b.y, n0, a.w);
    }

    float4 bb = *reinterpret_cast<const float4*>(bias + hl * 4);
    a.x = fmaxf(a.x + bb.x, 0.f);
    a.y = fmaxf(a.y + bb.y, 0.f);
    a.z = fmaxf(a.z + bb.z, 0.f);
    a.w = fmaxf(a.w + bb.w, 0.f);
    *reinterpret_cast<float4*>(&out[(size_t)node * FOUT + hl * 4]) = a;
}

// ---------------------------------------------------------------------------
// Launch topology: fork/join as before, but gemm is the 4th API launch so
// ncu profiles it (stream deps, not API order, define the graph).
extern "C" void kernel_launch(void* const* d_in, const int* in_sizes, int n_in,
                              void* d_out, int out_size)
{
    const float* x   = (const float*)d_in[0];   // [N, 256]
    const int*   adj = (const int*)d_in[1];     // [2, E]
    const float* W   = (const float*)d_in[2];   // [256, 64]
    const float* b   = (const float*)d_in[3];   // [64]
    float*       out = (float*)d_out;           // [N, 64]

    const int* src = adj;
    const int* dst = adj + EE;

    static cudaStream_t s2 = nullptr;
    static cudaEvent_t evF = nullptr, evJ = nullptr;
    if (!s2) {
        cudaStreamCreateWithFlags(&s2, cudaStreamNonBlocking);
        cudaEventCreateWithFlags(&evF, cudaEventDisableTiming);
        cudaEventCreateWithFlags(&evJ, cudaEventDisableTiming);
        cudaFuncSetAttribute(k_gemm_mma,
                             cudaFuncAttributeMaxDynamicSharedMemorySize, GEMM_SMEM);
    }

    // fork
    cudaEventRecord(evF, 0);
    cudaStreamWaitEvent(s2, evF, 0);

    // s2: first part of CSR build
    k_zero<<<(NN + 255) / 256, 256, 0, s2>>>();
    k_count<<<(EE / 4 + 255) / 256, 256, 0, s2>>>(dst);
    k_scan_a<<<NBLK, 1024, 0, s2>>>();

    // main: GEMM — 4th API launch (profiled)
    k_gemm_mma<<<(NN + 127) / 128, 512, GEMM_SMEM>>>(x, W);

    // s2: rest of CSR build
    k_scan_c<<<NBLK, 1024, 0, s2>>>();
    k_fill<<<(EE / 4 + 255) / 256, 256, 0, s2>>>(src, dst);
    cudaEventRecord(evJ, s2);

    // join: gather needs both branches
    cudaStreamWaitEvent(0, evJ, 0);
    k_gather<<<(NN / 2 + 7) / 8, 256>>>(b, out);
}

// round 15
// speedup vs baseline: 1.3598x; 1.3598x over previous
#include <cuda_runtime.h>
#include <cuda_bf16.h>
#include <cuda_fp16.h>
#include <cstdint>

// Problem constants (match reference_code)
#define NN 50000
#define EE 800000
#define FIN 256
#define FOUT 64

#define NBLK 49   // ceil(NN / 1024)

// Scratch (no cudaMalloc allowed) — static __device__ globals.
__device__ int    g_cnt[NN];          // in-degree (w/o self loop)
__device__ int    g_fill[NN];         // bucket fill cursor (pre-init to offsets)
__device__ int    g_off[NN + 1];      // CSR offsets
__device__ int    g_bsum[64];         // per-block sums for scan
__device__ int    g_nbr[EE];          // CSR: src node per incoming edge (4B/edge)
__device__ float  g_deg[NN];          // dinv = rsqrt(deg)
__device__ __half g_h16[NN * FOUT];   // h = x @ W, fp16 (128B per row)

// ---------------------------------------------------------------------------
__device__ __forceinline__ uint32_t pk2(float lo, float hi) {
    uint32_t d;
    asm("cvt.rn.bf16x2.f32 %0, %1, %2;" : "=r"(d) : "f"(hi), "f"(lo));
    return d;
}
__device__ __forceinline__ float f_lo16(uint32_t u) { return __uint_as_float(u << 16); }
__device__ __forceinline__ float f_hi16(uint32_t u) { return __uint_as_float(u & 0xffff0000u); }

__device__ __forceinline__ void mma_bf16(float* c, const uint32_t* a, uint32_t b0, uint32_t b1) {
    asm volatile(
        "mma.sync.aligned.m16n8k16.row.col.f32.bf16.bf16.f32 "
        "{%0,%1,%2,%3}, {%4,%5,%6,%7}, {%8,%9}, {%0,%1,%2,%3};"
        : "+f"(c[0]), "+f"(c[1]), "+f"(c[2]), "+f"(c[3])
        : "r"(a[0]), "r"(a[1]), "r"(a[2]), "r"(a[3]), "r"(b0), "r"(b1));
}

// ---------------------------------------------------------------------------
// K1: zero counters
__global__ void k_zero() {
    int i = blockIdx.x * blockDim.x + threadIdx.x;
    if (i < NN) g_cnt[i] = 0;
}

// K2: in-degree count over edge dst (4 edges/thread, int4 loads)
__global__ void k_count(const int* __restrict__ dst) {
    int e0 = (blockIdx.x * blockDim.x + threadIdx.x) * 4;
    if (e0 >= EE) return;
    int4 d4 = *reinterpret_cast<const int4*>(dst + e0);
    atomicAdd(&g_cnt[d4.x], 1);
    atomicAdd(&g_cnt[d4.y], 1);
    atomicAdd(&g_cnt[d4.z], 1);
    atomicAdd(&g_cnt[d4.w], 1);
}

// K3a: per-block (1024 elems) sums, coalesced
__global__ __launch_bounds__(1024) void k_scan_a() {
    __shared__ int ws[32];
    const int t = threadIdx.x;
    int idx = blockIdx.x * 1024 + t;
    int v = (idx < NN) ? g_cnt[idx] : 0;
    for (int o = 16; o > 0; o >>= 1) v += __shfl_down_sync(0xffffffffu, v, o);
    if ((t & 31) == 0) ws[t >> 5] = v;
    __syncthreads();
    if (t < 32) {
        int s = ws[t];
        for (int o = 16; o > 0; o >>= 1) s += __shfl_down_sync(0xffffffffu, s, o);
        if (t == 0) g_bsum[blockIdx.x] = s;
    }
}

// K3b: per-block exclusive scan -> g_off, g_fill (cursor), g_deg.
__global__ __launch_bounds__(1024) void k_scan_c() {
    __shared__ int ws[32];
    __shared__ int bpre_s;
    const int t = threadIdx.x;
    const int lane = t & 31;
    const int wid = t >> 5;
    int idx = blockIdx.x * 1024 + t;
    int c = (idx < NN) ? g_cnt[idx] : 0;

    int incl = c;
    for (int o = 1; o < 32; o <<= 1) {
        int u = __shfl_up_sync(0xffffffffu, incl, o);
        if (lane >= o) incl += u;
    }
    if (lane == 31) ws[wid] = incl;

    if (wid == 1) {
        int accp = 0;
        for (int j = lane; j < blockIdx.x; j += 32) accp += g_bsum[j];
        for (int o = 16; o > 0; o >>= 1) accp += __shfl_down_sync(0xffffffffu, accp, o);
        if (lane == 0) bpre_s = accp;
    }
    __syncthreads();
    if (wid == 0) {
        int wv = ws[lane];
        for (int o = 1; o < 32; o <<= 1) {
            int u = __shfl_up_sync(0xffffffffu, wv, o);
            if (lane >= o) wv += u;
        }
        ws[lane] = wv;
    }
    __syncthreads();
    int excl = incl - c + (wid ? ws[wid - 1] : 0);

    if (idx < NN) {
        int off = bpre_s + excl;
        g_off[idx]  = off;
        g_fill[idx] = off;
        g_deg[idx]  = rsqrtf((float)(c + 1));
    }
    if (blockIdx.x == 0 && t == 0) g_off[NN] = EE;
}

// K4: bucket fill — cursor holds offsets; 4 edges/thread; 4B/edge store.
__global__ void k_fill(const int* __restrict__ src, const int* __restrict__ dst) {
    int e0 = (blockIdx.x * blockDim.x + threadIdx.x) * 4;
    if (e0 >= EE) return;
    int4 s4 = *reinterpret_cast<const int4*>(src + e0);
    int4 d4 = *reinterpret_cast<const int4*>(dst + e0);
    int p0 = atomicAdd(&g_fill[d4.x], 1);
    int p1 = atomicAdd(&g_fill[d4.y], 1);
    int p2 = atomicAdd(&g_fill[d4.z], 1);
    int p3 = atomicAdd(&g_fill[d4.w], 1);
    g_nbr[p0] = s4.x;
    g_nbr[p1] = s4.y;
    g_nbr[p2] = s4.z;
    g_nbr[p3] = s4.w;
}

// ---------------------------------------------------------------------------
// K5: mma.sync bf16 GEMM, split-bf16, permuted-K fragments — EXACT revert to
// the 71.7µs version (no software pipeline).

#define PAD_K 272
#define B_HI_OFF 0
#define B_LO_OFF (64 * PAD_K)               // in ushort units
#define GEMM_SMEM (2 * 64 * PAD_K * 2)      // bytes = 69632

__global__ __launch_bounds__(512, 2) void k_gemm_mma(
    const float* __restrict__ x, const float* __restrict__ W)
{
    extern __shared__ __align__(16) ushort Bs[];   // [2][64][PAD_K] bf16 bits

    const int t    = threadIdx.x;
    const int wid  = t >> 5;
    const int lane = t & 31;
    const int g    = lane >> 2;
    const int tig  = lane & 3;

    // ---- stage W -> smem bf16 hi/lo, [n][k] layout ----
#pragma unroll 8
    for (int it = 0; it < 32; ++it) {
        int idx = t + it * 512;
        int k = idx >> 6;
        int n = idx & 63;
        float w = W[k * FOUT + n];
        uint32_t hp = pk2(w, 0.f);
        Bs[B_HI_OFF + n * PAD_K + k] = (ushort)(hp & 0xffffu);
        Bs[B_LO_OFF + n * PAD_K + k] =
            (ushort)(pk2(w - f_lo16(hp), 0.f) & 0xffffu);
    }
    __syncthreads();

    const int stripe = wid & 7;
    const int nhalf  = wid >> 3;
    const int row0   = blockIdx.x * 128 + stripe * 16;

    const int row1 = row0 + g;
    const int row2 = row1 + 8;
    const bool v1 = (row1 < NN);
    const bool v2 = (row2 < NN);
    const float* xr1 = x + (size_t)row1 * FIN;
    const float* xr2 = x + (size_t)row2 * FIN;

    float acc[4][4];
#pragma unroll
    for (int i = 0; i < 4; ++i)
#pragma unroll
        for (int j = 0; j < 4; ++j) acc[i][j] = 0.0f;

#pragma unroll 4
    for (int s = 0; s < 16; ++s) {
        const int kb4 = s * 16 + tig * 4;    // permuted-k fragment base

        float4 q1 = v1 ? *reinterpret_cast<const float4*>(xr1 + kb4)
                       : make_float4(0.f, 0.f, 0.f, 0.f);
        float4 q2 = v2 ? *reinterpret_cast<const float4*>(xr2 + kb4)
                       : make_float4(0.f, 0.f, 0.f, 0.f);

        uint32_t a_hi[4], a_lo[4];
        a_hi[0] = pk2(q1.x, q1.y); a_lo[0] = pk2(q1.x - f_lo16(a_hi[0]), q1.y - f_hi16(a_hi[0]));
        a_hi[1] = pk2(q2.x, q2.y); a_lo[1] = pk2(q2.x - f_lo16(a_hi[1]), q2.y - f_hi16(a_hi[1]));
        a_hi[2] = pk2(q1.z, q1.w); a_lo[2] = pk2(q1.z - f_lo16(a_hi[2]), q1.w - f_hi16(a_hi[2]));
        a_hi[3] = pk2(q2.z, q2.w); a_lo[3] = pk2(q2.z - f_lo16(a_hi[3]), q2.w - f_hi16(a_hi[3]));

#pragma unroll
        for (int nt = 0; nt < 4; ++nt) {
            int n = nhalf * 32 + nt * 8 + g;
            uint2 bh = *reinterpret_cast<const uint2*>(&Bs[B_HI_OFF + n * PAD_K + kb4]);
            uint2 bl = *reinterpret_cast<const uint2*>(&Bs[B_LO_OFF + n * PAD_K + kb4]);
            mma_bf16(acc[nt], a_hi, bh.x, bh.y);
            mma_bf16(acc[nt], a_hi, bl.x, bl.y);
            mma_bf16(acc[nt], a_lo, bh.x, bh.y);
        }
    }

    // ---- epilogue: write h as fp16 ----
#pragma unroll
    for (int nt = 0; nt < 4; ++nt) {
        int c0 = nhalf * 32 + nt * 8 + tig * 2;
        if (v1) {
            __half2 hv = __floats2half2_rn(acc[nt][0], acc[nt][1]);
            *reinterpret_cast<__half2*>(&g_h16[(size_t)row1 * FOUT + c0]) = hv;
        }
        if (v2) {
            __half2 hv = __floats2half2_rn(acc[nt][2], acc[nt][3]);
            *reinterpret_cast<__half2*>(&g_h16[(size_t)row2 * FOUT + c0]) = hv;
        }
    }
}

// ---------------------------------------------------------------------------
// K6: CSR gather on fp16 h. 2 nodes/warp, fp32 accumulation, x4 unroll.
// ONLY change vs 71.7µs version: the serial remainder (≤3 dependent-load
// chains) becomes ONE predicated parallel batch (clamped idx, zero weight).
__global__ __launch_bounds__(256) void k_gather(
    const float* __restrict__ bias, float* __restrict__ out)
{
    const int warp = blockIdx.x * 8 + (threadIdx.x >> 5);
    const int lane = threadIdx.x & 31;
    const int half = lane >> 4;
    const int hl   = lane & 15;
    const int node = warp * 2 + half;
    if (node >= NN) return;

    const float dinv = g_deg[node];
    const int beg = g_off[node];
    const int end = g_off[node + 1];

    uint2 su = *reinterpret_cast<const uint2*>(&g_h16[(size_t)node * FOUT + hl * 4]);
    float2 s01 = __half22float2(*reinterpret_cast<__half2*>(&su.x));
    float2 s23 = __half22float2(*reinterpret_cast<__half2*>(&su.y));
    const float sl = dinv * dinv;
    float4 a = make_float4(s01.x * sl, s01.y * sl, s23.x * sl, s23.y * sl);

    int j = beg;
    for (; j + 4 <= end; j += 4) {
        int s0 = g_nbr[j];
        int s1 = g_nbr[j + 1];
        int s2 = g_nbr[j + 2];
        int s3 = g_nbr[j + 3];
        float n0 = dinv * g_deg[s0];
        float n1 = dinv * g_deg[s1];
        float n2 = dinv * g_deg[s2];
        float n3 = dinv * g_deg[s3];
        uint2 u0 = *reinterpret_cast<const uint2*>(&g_h16[(size_t)s0 * FOUT + hl * 4]);
        uint2 u1 = *reinterpret_cast<const uint2*>(&g_h16[(size_t)s1 * FOUT + hl * 4]);
        uint2 u2 = *reinterpret_cast<const uint2*>(&g_h16[(size_t)s2 * FOUT + hl * 4]);
        uint2 u3 = *reinterpret_cast<const uint2*>(&g_h16[(size_t)s3 * FOUT + hl * 4]);

        float2 f0a = __half22float2(*reinterpret_cast<__half2*>(&u0.x));
        float2 f0b = __half22float2(*reinterpret_cast<__half2*>(&u0.y));
        a.x = fmaf(f0a.x, n0, a.x); a.y = fmaf(f0a.y, n0, a.y);
        a.z = fmaf(f0b.x, n0, a.z); a.w = fmaf(f0b.y, n0, a.w);

        float2 f1a = __half22float2(*reinterpret_cast<__half2*>(&u1.x));
        float2 f1b = __half22float2(*reinterpret_cast<__half2*>(&u1.y));
        a.x = fmaf(f1a.x, n1, a.x); a.y = fmaf(f1a.y, n1, a.y);
        a.z = fmaf(f1b.x, n1, a.z); a.w = fmaf(f1b.y, n1, a.w);

        float2 f2a = __half22float2(*reinterpret_cast<__half2*>(&u2.x));
        float2 f2b = __half22float2(*reinterpret_cast<__half2*>(&u2.y));
        a.x = fmaf(f2a.x, n2, a.x); a.y = fmaf(f2a.y, n2, a.y);
        a.z = fmaf(f2b.x, n2, a.z); a.w = fmaf(f2b.y, n2, a.w);

        float2 f3a = __half22float2(*reinterpret_cast<__half2*>(&u3.x));
        float2 f3b = __half22float2(*reinterpret_cast<__half2*>(&u3.y));
        a.x = fmaf(f3a.x, n3, a.x); a.y = fmaf(f3a.y, n3, a.y);
        a.z = fmaf(f3b.x, n3, a.z); a.w = fmaf(f3b.y, n3, a.w);
    }
    if (j < end) {
        // predicated parallel tail: clamp idx, zero weight for padding
        int i0 = j,     i1 = j + 1, i2 = j + 2;
        int s0 = g_nbr[i0];
        int s1 = g_nbr[(i1 < end) ? i1 : i0];
        int s2 = g_nbr[(i2 < end) ? i2 : i0];
        float n0 = dinv * g_deg[s0];
        float n1 = (i1 < end) ? dinv * g_deg[s1] : 0.f;
        float n2 = (i2 < end) ? dinv * g_deg[s2] : 0.f;
        uint2 u0 = *reinterpret_cast<const uint2*>(&g_h16[(size_t)s0 * FOUT + hl * 4]);
        uint2 u1 = *reinterpret_cast<const uint2*>(&g_h16[(size_t)s1 * FOUT + hl * 4]);
        uint2 u2 = *reinterpret_cast<const uint2*>(&g_h16[(size_t)s2 * FOUT + hl * 4]);
        float2 f0a = __half22float2(*reinterpret_cast<__half2*>(&u0.x));
        float2 f0b = __half22float2(*reinterpret_cast<__half2*>(&u0.y));
        float2 f1a = __half22float2(*reinterpret_cast<__half2*>(&u1.x));
        float2 f1b = __half22float2(*reinterpret_cast<__half2*>(&u1.y));
        float2 f2a = __half22float2(*reinterpret_cast<__half2*>(&u2.x));
        float2 f2b = __half22float2(*reinterpret_cast<__half2*>(&u2.y));
        a.x = fmaf(f0a.x, n0, a.x); a.y = fmaf(f0a.y, n0, a.y);
        a.z = fmaf(f0b.x, n0, a.z); a.w = fmaf(f0b.y, n0, a.w);
        a.x = fmaf(f1a.x, n1, a.x); a.y = fmaf(f1a.y, n1, a.y);
        a.z = fmaf(f1b.x, n1, a.z); a.w = fmaf(f1b.y, n1, a.w);
        a.x = fmaf(f2a.x, n2, a.x); a.y = fmaf(f2a.y, n2, a.y);
        a.z = fmaf(f2b.x, n2, a.z); a.w = fmaf(f2b.y, n2, a.w);
    }

    float4 bb = *reinterpret_cast<const float4*>(bias + hl * 4);
    a.x = fmaxf(a.x + bb.x, 0.f);
    a.y = fmaxf(a.y + bb.y, 0.f);
    a.z = fmaxf(a.z + bb.z, 0.f);
    a.w = fmaxf(a.w + bb.w, 0.f);
    *reinterpret_cast<float4*>(&out[(size_t)node * FOUT + hl * 4]) = a;
}

// ---------------------------------------------------------------------------
// Launch topology: fork/join; gemm is the 4th API launch (profiled).
extern "C" void kernel_launch(void* const* d_in, const int* in_sizes, int n_in,
                              void* d_out, int out_size)
{
    const float* x   = (const float*)d_in[0];   // [N, 256]
    const int*   adj = (const int*)d_in[1];     // [2, E]
    const float* W   = (const float*)d_in[2];   // [256, 64]
    const float* b   = (const float*)d_in[3];   // [64]
    float*       out = (float*)d_out;           // [N, 64]

    const int* src = adj;
    const int* dst = adj + EE;

    static cudaStream_t s2 = nullptr;
    static cudaEvent_t evF = nullptr, evJ = nullptr;
    if (!s2) {
        cudaStreamCreateWithFlags(&s2, cudaStreamNonBlocking);
        cudaEventCreateWithFlags(&evF, cudaEventDisableTiming);
        cudaEventCreateWithFlags(&evJ, cudaEventDisableTiming);
        cudaFuncSetAttribute(k_gemm_mma,
                             cudaFuncAttributeMaxDynamicSharedMemorySize, GEMM_SMEM);
    }

    // fork
    cudaEventRecord(evF, 0);
    cudaStreamWaitEvent(s2, evF, 0);

    // s2: first part of CSR build
    k_zero<<<(NN + 255) / 256, 256, 0, s2>>>();
    k_count<<<(EE / 4 + 255) / 256, 256, 0, s2>>>(dst);
    k_scan_a<<<NBLK, 1024, 0, s2>>>();

    // main: GEMM — 4th API launch (profiled)
    k_gemm_mma<<<(NN + 127) / 128, 512, GEMM_SMEM>>>(x, W);

    // s2: rest of CSR build
    k_scan_c<<<NBLK, 1024, 0, s2>>>();
    k_fill<<<(EE / 4 + 255) / 256, 256, 0, s2>>>(src, dst);
    cudaEventRecord(evJ, s2);

    // join: gather needs both branches
    cudaStreamWaitEvent(0, evJ, 0);
    k_gather<<<(NN / 2 + 7) / 8, 256>>>(b, out);
}